// round 16
// baseline (speedup 1.0000x reference)
#include <cuda_runtime.h>
#include <cuda_fp16.h>
#include <math.h>

#define HH 512
#define WW 512
#define HW (512*512)
#define NB 8
#define NC 3
#define NPIX (NB*NC*HW)
#define PI_F 3.14159265358979f
#define CIP 40

// ---------------- scratch (device globals; no allocations) ----------------
__device__ __half g_H16[NB*32*HW];      // 128 MB phase-head hidden (fp16)
__device__ __half g_Hb[NB*32*HW];       // 128 MB y1 (mix conv1 raw out)
__device__ __half g_Y2[NB*32*HW];       // 128 MB y2 (mix conv2 raw out)
__device__ float2 g_U[NB*NC*HW];        // 50 MB  complex field
__device__ __half g_J[NB*NC*HW];        // 12.5 MB (fp16)
__device__ float  g_delta[NB*NC*HW];    // 25 MB
__device__ float2 g_twid[256];
__device__ double g_zsum[NB*NC];
__device__ double g_xs1[NB], g_xs2[NB];
__device__ float  g_xmu[NB], g_xrs[NB];
__device__ double g_s1y1[NB], g_s2y1[NB], g_s1y2[NB], g_s2y2[NB];
__device__ double g_psum[NB*NC];
__device__ float  g_wse[NB*NC];

__device__ __forceinline__ int rev9(int x){ return (int)(__brev((unsigned)x) >> 23); }
__device__ __forceinline__ float siluf(float v){ return v / (1.f + __expf(-v)); }
__device__ __forceinline__ float warpSum(float v){
    #pragma unroll
    for (int o=16;o;o>>=1) v += __shfl_down_sync(0xffffffffu, v, o);
    return v;
}
// ---- packed f32x2 helpers ----
__device__ __forceinline__ unsigned long long pk2(float a, float b){
    unsigned long long r;
    asm("mov.b64 %0, {%1, %2};" : "=l"(r) : "f"(a), "f"(b));
    return r;
}
__device__ __forceinline__ void upk2(unsigned long long v, float& a, float& b){
    asm("mov.b64 {%0, %1}, %2;" : "=f"(a), "=f"(b) : "l"(v));
}
__device__ __forceinline__ void fma2(unsigned long long& d, unsigned long long a, unsigned long long b){
    asm("fma.rn.f32x2 %0, %1, %2, %3;" : "=l"(d) : "l"(a), "l"(b), "l"(d));
}
__device__ __forceinline__ unsigned pkh(float a, float b){
    __half2 h = __floats2half2_rn(a, b);
    return *(unsigned*)&h;
}
__device__ __forceinline__ unsigned pkh2(__half a, __half b){
    __half2 h = __halves2half2(a, b);
    return *(unsigned*)&h;
}
__device__ __forceinline__ void mma16816(float* acc, unsigned a0, unsigned a1,
                                         unsigned a2, unsigned a3, unsigned b0, unsigned b1){
    asm volatile(
        "mma.sync.aligned.m16n8k16.row.col.f32.f16.f16.f32 "
        "{%0,%1,%2,%3}, {%4,%5,%6,%7}, {%8,%9}, {%0,%1,%2,%3};"
        : "+f"(acc[0]), "+f"(acc[1]), "+f"(acc[2]), "+f"(acc[3])
        : "r"(a0), "r"(a1), "r"(a2), "r"(a3), "r"(b0), "r"(b1));
}

// ---------------- init ----------------
__global__ void k_init(){
    int t = threadIdx.x;
    if (t < 256){
        double ang = -2.0*3.14159265358979323846*(double)t/512.0;
        g_twid[t] = make_float2((float)cos(ang), (float)sin(ang));
    }
    if (t < NB*NC){ g_zsum[t]=0.0; g_psum[t]=0.0; }
    if (t < NB){
        g_s1y1[t]=0.0; g_s2y1[t]=0.0; g_s1y2[t]=0.0; g_s2y2[t]=0.0;
        g_xs1[t]=0.0; g_xs2[t]=0.0;
    }
}

// ---------------- x groupnorm stats (per batch), wide grid ----------------
__global__ void k_xstats1(const float* __restrict__ x){
    int b = blockIdx.y, t = threadIdx.x;
    const float4* p = (const float4*)(x + (size_t)b*NC*HW);
    float s=0.f, ss=0.f;
    for (int i = blockIdx.x*256 + t; i < NC*HW/4; i += 48*256){
        float4 v = p[i];
        s  += v.x+v.y+v.z+v.w;
        ss += v.x*v.x+v.y*v.y+v.z*v.z+v.w*v.w;
    }
    __shared__ float r1[8], r2[8];
    float w1 = warpSum(s), w2 = warpSum(ss);
    int lane=t&31, wid=t>>5;
    if (lane==0){ r1[wid]=w1; r2[wid]=w2; }
    __syncthreads();
    if (t==0){
        float a=0.f, bb=0.f;
        #pragma unroll
        for (int i=0;i<8;i++){ a+=r1[i]; bb+=r2[i]; }
        atomicAdd(&g_xs1[b], (double)a);
        atomicAdd(&g_xs2[b], (double)bb);
    }
}
__global__ void k_xstats2(){
    int t = threadIdx.x;
    if (t < NB){
        double N = (double)(NC*HW);
        double mu = g_xs1[t]/N;
        double var = g_xs2[t]/N - mu*mu;
        g_xmu[t] = (float)mu;
        g_xrs[t] = rsqrtf((float)var + 1e-5f);
    }
}

// ---- conv1 FFMA2 (validated 149us): xn(3)->32ch silu fp16; 16x16 tile, 4px x 8co ----
__global__ __launch_bounds__(256,3) void k_conv1(const float* __restrict__ x,
                        const float* __restrict__ ng, const float* __restrict__ nbv,
                        const float* __restrict__ pw1, const float* __restrict__ pb1,
                        const float* __restrict__ zw1, const float* __restrict__ zb1){
    __shared__ __align__(16) float s_in[3*360];   // 3ci x 18row x 20col(pad)
    __shared__ __align__(16) float s_w[27*32];
    __shared__ float s_b[32];
    __shared__ float s_sc[3], s_sh[3];
    int b = blockIdx.z;
    int t = threadIdx.x;
    int qx = t&3, ty = (t>>2)&15, cg = t>>6;
    int oy0 = blockIdx.y*16, ox0 = blockIdx.x*16;
    if (t < 3){
        float rs = g_xrs[b], mu = g_xmu[b];
        s_sc[t] = ng[t]*rs;
        s_sh[t] = nbv[t] - mu*rs*ng[t];
    }
    for (int g=t; g<864; g+=256){
        int co=g/27, r=g%27;
        float w = (co<16) ? pw1[g] : zw1[(co-16)*27+r];
        s_w[r*32+co] = w;
    }
    if (t<32) s_b[t] = (t<16) ? pb1[t] : zb1[t-16];
    __syncthreads();
    for (int g=t; g<3*360; g+=256){
        int ci=g/360, r=g%360, iy=r/20, ix=r%20;
        int gy=oy0+iy-1, gx=ox0+ix-1;
        float v = 0.f;
        if (ix<18 && gy>=0 && gy<HH && gx>=0 && gx<WW)
            v = x[(size_t)(b*3+ci)*HW + gy*WW + gx]*s_sc[ci] + s_sh[ci];
        s_in[g] = v;
    }
    __syncthreads();
    unsigned long long acc[4][4];
    #pragma unroll
    for (int c=0;c<4;c++){
        unsigned long long bb = pk2(s_b[cg*8+2*c], s_b[cg*8+2*c+1]);
        #pragma unroll
        for (int p=0;p<4;p++) acc[c][p]=bb;
    }
    #pragma unroll
    for (int ci=0;ci<3;ci++)
    #pragma unroll
    for (int ky=0;ky<3;ky++){
        const float* row = s_in + ci*360 + (ty+ky)*20 + 4*qx;
        float4 f0 = *(const float4*)row;
        float2 f1 = *(const float2*)(row+4);
        unsigned long long vv[6];
        vv[0]=pk2(f0.x,f0.x); vv[1]=pk2(f0.y,f0.y); vv[2]=pk2(f0.z,f0.z);
        vv[3]=pk2(f0.w,f0.w); vv[4]=pk2(f1.x,f1.x); vv[5]=pk2(f1.y,f1.y);
        #pragma unroll
        for (int kx=0;kx<3;kx++){
            const unsigned long long* wr = (const unsigned long long*)(s_w + (ci*9+ky*3+kx)*32) + cg*4;
            #pragma unroll
            for (int c=0;c<4;c++){
                unsigned long long w = wr[c];
                fma2(acc[c][0], vv[kx],   w);
                fma2(acc[c][1], vv[kx+1], w);
                fma2(acc[c][2], vv[kx+2], w);
                fma2(acc[c][3], vv[kx+3], w);
            }
        }
    }
    int gy=oy0+ty, gx0=ox0+4*qx;
    size_t base = (size_t)b*32*HW + gy*WW + gx0;
    #pragma unroll
    for (int c=0;c<4;c++){
        int co0 = cg*8+2*c, co1 = co0+1;
        float a0[4], a1[4];
        #pragma unroll
        for (int p=0;p<4;p++) upk2(acc[c][p], a0[p], a1[p]);
        *(__half2*)(&g_H16[base + (size_t)co0*HW])     = __floats2half2_rn(siluf(a0[0]), siluf(a0[1]));
        *(__half2*)(&g_H16[base + (size_t)co0*HW + 2]) = __floats2half2_rn(siluf(a0[2]), siluf(a0[3]));
        *(__half2*)(&g_H16[base + (size_t)co1*HW])     = __floats2half2_rn(siluf(a1[0]), siluf(a1[1]));
        *(__half2*)(&g_H16[base + (size_t)co1*HW + 2]) = __floats2half2_rn(siluf(a1[2]), siluf(a1[3]));
    }
}

// ---- headout via HMMA: M=512px, N=8 (p0,z0,p1,z1,p2,z2,pad,pad), K=32x9taps ----
__global__ __launch_bounds__(256,3) void k_headout(const float* __restrict__ x,
                          const float* __restrict__ pw2, const float* __restrict__ pb2,
                          const float* __restrict__ zw2, const float* __restrict__ zb2){
    extern __shared__ __half smho[];
    __half* s_in = smho;                     // [612][40]
    __half* s_w  = smho + 612*40;            // [tap9][co8][40]
    float*  s_bz = (float*)(s_w + 2880);     // 8
    __shared__ float s_rz[3][8];
    int b = blockIdx.z;
    int t = threadIdx.x, w = t>>5, lane = t&31;
    int g = lane>>2, q = lane&3;
    int oy0 = blockIdx.y*16, ox0 = blockIdx.x*32;
    if (t<8){
        float v=0.f;
        if (t<6){ int c=t>>1; v = (t&1) ? zb2[c] : pb2[c]; }
        s_bz[t]=v;
    }
    for (int e=t; e<2880; e+=256){
        int tap=e/320, r=e%320, co=r/40, ci=r%40;
        float v=0.f;
        if (ci<32 && co<6){
            int c = co>>1;
            v = (co&1) ? zw2[c*144 + ci*9 + tap] : pw2[c*144 + ci*9 + tap];
        }
        s_w[e] = __float2half(v);
    }
    for (int e=t; e<612; e+=256){
        int iy=e/34, ix=e%34;
        int gy=oy0+iy-1, gx=ox0+ix-1;
        bool in = (gy>=0 && gy<HH && gx>=0 && gx<WW);
        size_t p0 = (size_t)b*32*HW + (size_t)gy*WW + gx;
        __half h[32];
        #pragma unroll
        for (int ci=0;ci<32;ci++)
            h[ci] = in ? g_H16[p0 + (size_t)ci*HW] : __float2half(0.f);
        uint4* dst = (uint4*)(s_in + e*40);
        #pragma unroll
        for (int k2=0;k2<4;k2++)
            dst[k2] = make_uint4(pkh2(h[k2*8],h[k2*8+1]),   pkh2(h[k2*8+2],h[k2*8+3]),
                                 pkh2(h[k2*8+4],h[k2*8+5]), pkh2(h[k2*8+6],h[k2*8+7]));
    }
    __syncthreads();
    float acc[4][4];
    #pragma unroll
    for (int mt=0;mt<4;mt++)
    #pragma unroll
    for (int i=0;i<4;i++) acc[mt][i]=0.f;
    #pragma unroll
    for (int tap=0; tap<9; tap++){
        int ky=tap/3, kx=tap%3;
        #pragma unroll
        for (int kc=0; kc<2; kc++){
            const __half* wp = s_w + tap*320 + g*40 + kc*16 + q*2;
            unsigned b0 = *(const unsigned*)wp;
            unsigned b1 = *(const unsigned*)(wp+8);
            #pragma unroll
            for (int mt=0;mt<4;mt++){
                int yy = 2*w + (mt>>1) + ky;
                int xx = (mt&1)*16 + kx + g;
                const __half* ap = s_in + (yy*34 + xx)*40 + kc*16 + q*2;
                unsigned a0 = *(const unsigned*)ap;
                unsigned a1 = *(const unsigned*)(ap + 8*40);
                unsigned a2 = *(const unsigned*)(ap + 8);
                unsigned a3 = *(const unsigned*)(ap + 8*40 + 8);
                mma16816(acc[mt], a0, a1, a2, a3, b0, b1);
            }
        }
    }
    float zacc = 0.f;
    if (q < 3){
        float bp = s_bz[2*q], bz = s_bz[2*q+1];
        #pragma unroll
        for (int mt=0;mt<4;mt++){
            int yy = oy0 + 2*w + (mt>>1);
            int xb = ox0 + (mt&1)*16 + g;
            size_t pos = (size_t)(b*3+q)*HW + (size_t)yy*WW + xb;
            {
                float phi = tanhf(acc[mt][0]+bp)*PI_F;
                float sn, cs; __sincosf(phi, &sn, &cs);
                float xv = x[pos];
                g_U[pos] = make_float2(xv*cs, xv*sn);
                zacc += 0.3f/(1.f+__expf(-(acc[mt][1]+bz)));
            }
            {
                float phi = tanhf(acc[mt][2]+bp)*PI_F;
                float sn, cs; __sincosf(phi, &sn, &cs);
                float xv = x[pos+8];
                g_U[pos+8] = make_float2(xv*cs, xv*sn);
                zacc += 0.3f/(1.f+__expf(-(acc[mt][3]+bz)));
            }
        }
    }
    #pragma unroll
    for (int o=16;o>=4;o>>=1) zacc += __shfl_down_sync(0xffffffffu, zacc, o);
    if (lane<3) s_rz[lane][w] = zacc;
    __syncthreads();
    if (t==0){
        #pragma unroll
        for (int c=0;c<3;c++){
            float s=0.f;
            #pragma unroll
            for (int i=0;i<8;i++) s+=s_rz[c][i];
            atomicAdd(&g_zsum[b*3+c], (double)s);
        }
    }
}

// ---------------- 512-pt FFT core (AoS, rows) ----------------
__device__ __forceinline__ void fft512(float2* s, const float2* tw, int t, bool inv){
    #pragma unroll
    for (int st=1; st<=9; st++){
        int half = 1<<(st-1);
        int grp = t >> (st-1);
        int j   = t & (half-1);
        int i   = (grp << st) + j;
        float2 w = tw[j << (9-st)];
        float wy = inv ? -w.y : w.y;
        float2 u = s[i], v = s[i+half];
        float vr = v.x*w.x - v.y*wy;
        float vi = v.x*wy + v.y*w.x;
        s[i]      = make_float2(u.x+vr, u.y+vi);
        s[i+half] = make_float2(u.x-vr, u.y-vi);
        __syncthreads();
    }
}

__global__ void k_fftrow_fwd(){
    __shared__ float2 s[512];
    __shared__ float2 tw[256];
    int t = threadIdx.x;
    size_t base = (size_t)blockIdx.x * 512;
    tw[t] = g_twid[t];
    float2 a = g_U[base+t], b = g_U[base+t+256];
    s[rev9(t)] = a; s[rev9(t+256)] = b;
    __syncthreads();
    fft512(s, tw, t, false);
    g_U[base+t] = s[t]; g_U[base+t+256] = s[t+256];
}

__global__ void k_ifftrow_mag(){
    __shared__ float2 s[512];
    __shared__ float2 tw[256];
    int t = threadIdx.x;
    size_t base = (size_t)blockIdx.x * 512;
    tw[t] = g_twid[t];
    float2 a = g_U[base+t], b = g_U[base+t+256];
    s[rev9(t)] = a; s[rev9(t+256)] = b;
    __syncthreads();
    fft512(s, tw, t, true);
    const float sc = 1.f/262144.f;
    #pragma unroll
    for (int e2=0;e2<2;e2++){
        int e = t + e2*256;
        float re = s[e].x*sc, im = s[e].y*sc;
        g_J[base+e] = __float2half(sqrtf(fmaxf(re*re+im*im, 1e-12f)));
    }
}

// ------- col FFT fwd + freq filter + col IFFT (8 cols/block, SoA pad 9) -------
__global__ void k_fftcol(const float* __restrict__ freq_gain){
    __shared__ float sRe[4608], sIm[4608];
    __shared__ float2 tw[256];
    int bid = blockIdx.x;
    int bc = bid>>6, cb = bid&63;
    int c = bc%3;
    int t = threadIdx.x;
    int cc = t&7, lr = t>>3;
    int col = cb*8 + cc;
    size_t base = (size_t)bc*HW;
    tw[t] = g_twid[t];
    #pragma unroll
    for (int k=0;k<16;k++){
        int r = lr + 32*k;
        float2 v = g_U[base + (size_t)r*WW + col];
        int rr = rev9(r);
        sRe[rr*9+cc] = v.x; sIm[rr*9+cc] = v.y;
    }
    __syncthreads();
    #pragma unroll
    for (int st=1; st<=9; st++){
        int half = 1<<(st-1);
        #pragma unroll
        for (int k=0;k<8;k++){
            int bf = lr + 32*k;
            int grp = bf >> (st-1), j = bf & (half-1);
            int i = (grp<<st) + j;
            float2 w = tw[j << (9-st)];
            int e0 = i*9+cc, e1 = (i+half)*9+cc;
            float ur=sRe[e0], ui=sIm[e0], vr0=sRe[e1], vi0=sIm[e1];
            float vr = vr0*w.x - vi0*w.y;
            float vi = vr0*w.y + vi0*w.x;
            sRe[e0]=ur+vr; sIm[e0]=ui+vi;
            sRe[e1]=ur-vr; sIm[e1]=ui-vi;
        }
        __syncthreads();
    }
    const float lam2inv = (c==0) ? (1.f/(0.65f*0.65f)) : (c==1) ? (1.f/(0.53f*0.53f)) : (1.f/(0.47f*0.47f));
    float zm = (float)(g_zsum[bc] * (1.0/262144.0));
    float gain = 1.f + freq_gain[c];
    float fx = (float)((col<256)?col:col-512) * (1.f/512.f);
    float fx2 = fx*fx;
    #pragma unroll
    for (int k=0;k<16;k++){
        int r = lr + 32*k;
        float fy = (float)((r<256)?r:r-512) * (1.f/512.f);
        float f2 = fy*fy + fx2;
        float kz = 6.28318530717958f * sqrtf(fmaxf(lam2inv - f2, 0.f));
        float hp = kz*zm;
        float sn, cs; __sincosf(hp, &sn, &cs);
        int e = r*9+cc;
        float re=sRe[e], im=sIm[e];
        sRe[e] = gain*(re*cs - im*sn);
        sIm[e] = gain*(re*sn + im*cs);
    }
    __syncthreads();
    #pragma unroll
    for (int k=0;k<16;k++){
        int r = lr + 32*k;
        int r2 = rev9(r);
        if (r < r2){
            int e=r*9+cc, e2=r2*9+cc;
            float a=sRe[e]; sRe[e]=sRe[e2]; sRe[e2]=a;
            float bb=sIm[e]; sIm[e]=sIm[e2]; sIm[e2]=bb;
        }
    }
    __syncthreads();
    #pragma unroll
    for (int st=1; st<=9; st++){
        int half = 1<<(st-1);
        #pragma unroll
        for (int k=0;k<8;k++){
            int bf = lr + 32*k;
            int grp = bf >> (st-1), j = bf & (half-1);
            int i = (grp<<st) + j;
            float2 w = tw[j << (9-st)];
            float wy = -w.y;
            int e0 = i*9+cc, e1 = (i+half)*9+cc;
            float ur=sRe[e0], ui=sIm[e0], vr0=sRe[e1], vi0=sIm[e1];
            float vr = vr0*w.x - vi0*wy;
            float vi = vr0*wy + vi0*w.x;
            sRe[e0]=ur+vr; sIm[e0]=ui+vi;
            sRe[e1]=ur-vr; sIm[e1]=ui-vi;
        }
        __syncthreads();
    }
    #pragma unroll
    for (int k=0;k<16;k++){
        int r = lr + 32*k;
        g_U[base + (size_t)r*WW + col] = make_float2(sRe[r*9+cc], sIm[r*9+cc]);
    }
}

// ---- mix conv1 via HMMA: [x,J_l,J_l-x_l](5, pad16) -> 32; 32x16 px tile ----
__global__ __launch_bounds__(256,2) void k_mixconv1(const float* __restrict__ x,
                           const float* __restrict__ w1, const float* __restrict__ b1){
    extern __shared__ __half smm1[];
    __half* s_in  = smm1;                   // [612][16]
    __half* s_out = smm1;                   // alias [32][512]
    __half* s_w   = smm1 + 16384;           // [tap9][co32][16]
    float*  s_b   = (float*)(s_w + 4608);
    __shared__ float s_r1[8], s_r2[8];
    int b = blockIdx.z;
    int t = threadIdx.x, w = t>>5, lane = t&31;
    int g = lane>>2, q = lane&3;
    int oy0 = blockIdx.y*16, ox0 = blockIdx.x*32;
    if (t<32) s_b[t]=b1[t];
    for (int e=t; e<4608; e+=256){
        int tap=e/512, r=e%512, co=r/16, ci=r%16;
        float v = (ci<5) ? w1[co*45 + ci*9 + tap] : 0.f;
        s_w[(tap*32+co)*16 + ci] = __float2half(v);
    }
    for (int e=t; e<612; e+=256){
        int iy=e/34, ix=e%34;
        int gy=oy0+iy-1, gx=ox0+ix-1;
        float x0=0,x1=0,x2=0,j0=0,j1=0,j2=0;
        if (gy>=0 && gy<HH && gx>=0 && gx<WW){
            size_t p = (size_t)b*3*HW + gy*WW + gx;
            x0=x[p]; x1=x[p+HW]; x2=x[p+2*HW];
            j0=__half2float(g_J[p]); j1=__half2float(g_J[p+HW]); j2=__half2float(g_J[p+2*HW]);
        }
        float xl = 0.299f*x0 + 0.587f*x1 + 0.114f*x2;
        float jl = 0.299f*j0 + 0.587f*j1 + 0.114f*j2;
        uint4* dst = (uint4*)(s_in + e*16);
        dst[0] = make_uint4(pkh(x0,x1), pkh(x2,jl), pkh(jl-xl,0.f), 0u);
        dst[1] = make_uint4(0u,0u,0u,0u);
    }
    __syncthreads();
    float acc[4][4][4];
    #pragma unroll
    for (int mt=0;mt<4;mt++)
    #pragma unroll
    for (int nt=0;nt<4;nt++)
    #pragma unroll
    for (int i=0;i<4;i++) acc[mt][nt][i]=0.f;
    #pragma unroll
    for (int tap=0; tap<9; tap++){
        int ky=tap/3, kx=tap%3;
        unsigned bf[4][2];
        #pragma unroll
        for (int nt=0;nt<4;nt++){
            const __half* wp = s_w + (tap*32 + nt*8 + g)*16 + q*2;
            bf[nt][0] = *(const unsigned*)(wp);
            bf[nt][1] = *(const unsigned*)(wp+8);
        }
        #pragma unroll
        for (int mt=0;mt<4;mt++){
            int yy = 2*w + (mt>>1) + ky;
            int xx = (mt&1)*16 + kx + g;
            const __half* ap = s_in + (yy*34 + xx)*16 + q*2;
            unsigned a0 = *(const unsigned*)ap;
            unsigned a1 = *(const unsigned*)(ap + 8*16);
            unsigned a2 = *(const unsigned*)(ap + 8);
            unsigned a3 = *(const unsigned*)(ap + 8*16 + 8);
            #pragma unroll
            for (int nt=0;nt<4;nt++)
                mma16816(acc[mt][nt], a0, a1, a2, a3, bf[nt][0], bf[nt][1]);
        }
    }
    float bias[4][2];
    #pragma unroll
    for (int nt=0;nt<4;nt++){
        bias[nt][0] = s_b[nt*8 + q*2];
        bias[nt][1] = s_b[nt*8 + q*2 + 1];
    }
    __syncthreads();
    float ls=0.f, lss=0.f;
    #pragma unroll
    for (int mt=0;mt<4;mt++){
        int yy = 2*w + (mt>>1);
        int x0 = (mt&1)*16;
        #pragma unroll
        for (int nt=0;nt<4;nt++){
            int co0 = nt*8 + q*2, co1 = co0+1;
            float v0 = acc[mt][nt][0] + bias[nt][0];
            float v1 = acc[mt][nt][1] + bias[nt][1];
            float v2 = acc[mt][nt][2] + bias[nt][0];
            float v3 = acc[mt][nt][3] + bias[nt][1];
            ls += v0+v1+v2+v3;
            lss += v0*v0+v1*v1+v2*v2+v3*v3;
            s_out[co0*512 + yy*32 + x0+g]   = __float2half(v0);
            s_out[co1*512 + yy*32 + x0+g]   = __float2half(v1);
            s_out[co0*512 + yy*32 + x0+g+8] = __float2half(v2);
            s_out[co1*512 + yy*32 + x0+g+8] = __float2half(v3);
        }
    }
    float w1s = warpSum(ls), w2s = warpSum(lss);
    if (lane==0){ s_r1[w]=w1s; s_r2[w]=w2s; }
    __syncthreads();
    if (t==0){
        float a=0.f, bb=0.f;
        #pragma unroll
        for (int i=0;i<8;i++){ a+=s_r1[i]; bb+=s_r2[i]; }
        atomicAdd(&g_s1y1[b], (double)a);
        atomicAdd(&g_s2y1[b], (double)bb);
    }
    for (int e=t; e<8192; e+=256){
        int co=e/256, r=e%256, yy=r/16, xh=r%16;
        *(__half2*)(&g_Hb[(size_t)(b*32+co)*HW + (size_t)(oy0+yy)*WW + ox0 + xh*2]) =
            *(const __half2*)(&s_out[co*512 + yy*32 + xh*2]);
    }
}

// ----- mix conv2: HMMA m16n8k16; 32x16 px tile, 9 shifted GEMMs, fp16 in/out -----
__global__ __launch_bounds__(256,2) void k_mixconv2(const float* __restrict__ w2, const float* __restrict__ b2,
                        const float* __restrict__ g1g, const float* __restrict__ g1b){
    extern __shared__ __half smh2[];
    __half* s_in = smh2;                         // [iy18][ix34][CIP40] halfs
    __half* s_w  = smh2 + 18*34*CIP;             // [tap9][co32][CIP40] halfs
    float*  s_A  = (float*)(s_w + 9*32*CIP);     // 32
    float*  s_B  = s_A + 32;                     // 32
    float*  s_bi = s_B + 32;                     // 32
    __shared__ float s_r1[8], s_r2[8];
    int b = blockIdx.z;
    int t = threadIdx.x, w = t>>5, lane = t&31;
    int g = lane>>2, q = lane&3;
    int oy0 = blockIdx.y*16, ox0 = blockIdx.x*32;
    if (t<32){
        double N = 8388608.0;
        double mu = g_s1y1[b]/N;
        double var = g_s2y1[b]/N - mu*mu;
        float rs = rsqrtf((float)var + 1e-5f);
        float A = rs*g1g[t];
        s_A[t]=A; s_B[t]=g1b[t]-(float)mu*A;
        s_bi[t]=b2[t];
    }
    for (int e=t; e<9216; e+=256){
        int co=e/288, r=e%288, ci=r/9, tap=r%9;
        s_w[(tap*32+co)*CIP + ci] = __float2half(w2[e]);
    }
    __syncthreads();
    for (int e=t; e<612; e+=256){
        int iy=e/34, ix=e%34;
        int gy=oy0+iy-1, gx=ox0+ix-1;
        bool in = (gy>=0 && gy<HH && gx>=0 && gx<WW);
        size_t p0 = (size_t)b*32*HW + (size_t)gy*WW + gx;
        float f[32];
        #pragma unroll
        for (int ci=0;ci<32;ci++){
            float v=0.f;
            if (in){
                float y = __half2float(g_Hb[p0 + (size_t)ci*HW]);
                v = siluf(y*s_A[ci] + s_B[ci]);
            }
            f[ci]=v;
        }
        uint4* dst = (uint4*)(s_in + e*CIP);
        #pragma unroll
        for (int k2=0;k2<4;k2++)
            dst[k2] = make_uint4(pkh(f[k2*8],f[k2*8+1]),   pkh(f[k2*8+2],f[k2*8+3]),
                                 pkh(f[k2*8+4],f[k2*8+5]), pkh(f[k2*8+6],f[k2*8+7]));
    }
    __syncthreads();
    float acc[4][4][4];
    #pragma unroll
    for (int mt=0;mt<4;mt++)
    #pragma unroll
    for (int nt=0;nt<4;nt++)
    #pragma unroll
    for (int i=0;i<4;i++) acc[mt][nt][i]=0.f;
    #pragma unroll
    for (int tap=0; tap<9; tap++){
        int ky=tap/3, kx=tap%3;
        #pragma unroll
        for (int kc=0; kc<2; kc++){
            unsigned bf[4][2];
            #pragma unroll
            for (int nt=0;nt<4;nt++){
                const __half* wp = s_w + (tap*32 + nt*8 + g)*CIP + kc*16 + q*2;
                bf[nt][0] = *(const unsigned*)(wp);
                bf[nt][1] = *(const unsigned*)(wp+8);
            }
            #pragma unroll
            for (int mt=0;mt<4;mt++){
                int yy = 2*w + (mt>>1) + ky;
                int xx = (mt&1)*16 + kx + g;
                const __half* ap = s_in + (yy*34 + xx)*CIP + kc*16 + q*2;
                unsigned a0 = *(const unsigned*)ap;
                unsigned a1 = *(const unsigned*)(ap + 8*CIP);
                unsigned a2 = *(const unsigned*)(ap + 8);
                unsigned a3 = *(const unsigned*)(ap + 8*CIP + 8);
                #pragma unroll
                for (int nt=0;nt<4;nt++)
                    mma16816(acc[mt][nt], a0, a1, a2, a3, bf[nt][0], bf[nt][1]);
            }
        }
    }
    float bias[4][2];
    #pragma unroll
    for (int nt=0;nt<4;nt++){
        bias[nt][0] = s_bi[nt*8 + q*2];
        bias[nt][1] = s_bi[nt*8 + q*2 + 1];
    }
    __syncthreads();
    __half* s_out = s_in;   // [co][y16][x32]
    float ls=0.f, lss=0.f;
    #pragma unroll
    for (int mt=0;mt<4;mt++){
        int yy = 2*w + (mt>>1);
        int x0 = (mt&1)*16;
        #pragma unroll
        for (int nt=0;nt<4;nt++){
            int co0 = nt*8 + q*2, co1 = co0+1;
            float v0 = acc[mt][nt][0] + bias[nt][0];
            float v1 = acc[mt][nt][1] + bias[nt][1];
            float v2 = acc[mt][nt][2] + bias[nt][0];
            float v3 = acc[mt][nt][3] + bias[nt][1];
            ls += v0+v1+v2+v3;
            lss += v0*v0+v1*v1+v2*v2+v3*v3;
            s_out[co0*512 + yy*32 + x0+g]   = __float2half(v0);
            s_out[co1*512 + yy*32 + x0+g]   = __float2half(v1);
            s_out[co0*512 + yy*32 + x0+g+8] = __float2half(v2);
            s_out[co1*512 + yy*32 + x0+g+8] = __float2half(v3);
        }
    }
    float w1s = warpSum(ls), w2s = warpSum(lss);
    if (lane==0){ s_r1[w]=w1s; s_r2[w]=w2s; }
    __syncthreads();
    if (t==0){
        float a=0.f, bb=0.f;
        #pragma unroll
        for (int i=0;i<8;i++){ a+=s_r1[i]; bb+=s_r2[i]; }
        atomicAdd(&g_s1y2[b], (double)a);
        atomicAdd(&g_s2y2[b], (double)bb);
    }
    for (int e=t; e<8192; e+=256){
        int co=e/256, r=e%256, yy=r/16, xh=r%16;
        *(__half2*)(&g_Y2[(size_t)(b*32+co)*HW + (size_t)(oy0+yy)*WW + ox0 + xh*2]) =
            *(const __half2*)(&s_out[co*512 + yy*32 + xh*2]);
    }
}

// ---------------- mix conv3 (1x1) -> delta + per-channel mean; 2px/thread ----------------
__global__ void k_mixconv3(const float* __restrict__ w3, const float* __restrict__ b3,
                           const float* __restrict__ g2g, const float* __restrict__ g2b){
    __shared__ float s_w[96], s_b3[3], s_A[32], s_B[32];
    __shared__ float s_r[8];
    int b = blockIdx.y;
    int t = threadIdx.x;
    int pix = (blockIdx.x*256 + t)*2;
    if (t<32){
        double N = 8388608.0;
        double mu = g_s1y2[b]/N;
        double var = g_s2y2[b]/N - mu*mu;
        float rs = rsqrtf((float)var + 1e-5f);
        float A = rs*g2g[t];
        s_A[t]=A; s_B[t]=g2b[t]-(float)mu*A;
    }
    if (t<96) s_w[t]=w3[t];
    if (t<3)  s_b3[t]=b3[t];
    __syncthreads();
    float a0=s_b3[0], a1=s_b3[1], a2=s_b3[2];
    float b0=s_b3[0], b1=s_b3[1], b2v=s_b3[2];
    size_t base = (size_t)b*32*HW + pix;
    #pragma unroll
    for (int ci=0;ci<32;ci++){
        __half2 h = *(const __half2*)(&g_Y2[base + (size_t)ci*HW]);
        float2 y = __half22float2(h);
        float A = s_A[ci], B = s_B[ci];
        float v0 = siluf(y.x*A + B);
        float v1 = siluf(y.y*A + B);
        float w0=s_w[ci], w1=s_w[32+ci], w2=s_w[64+ci];
        a0 += w0*v0; a1 += w1*v0; a2 += w2*v0;
        b0 += w0*v1; b1 += w1*v1; b2v += w2*v1;
    }
    size_t dbase = (size_t)b*3*HW + pix;
    *(float2*)(&g_delta[dbase])        = make_float2(a0, b0);
    *(float2*)(&g_delta[dbase+HW])     = make_float2(a1, b1);
    *(float2*)(&g_delta[dbase+2*HW])   = make_float2(a2, b2v);
    float av[3] = {a0+b0, a1+b1, a2+b2v};
    int lane=t&31, wid=t>>5;
    #pragma unroll
    for (int co=0;co<3;co++){
        float ws = warpSum(av[co]);
        if (lane==0) s_r[wid]=ws;
        __syncthreads();
        if (t==0){
            float s=0.f;
            #pragma unroll
            for (int i=0;i<8;i++) s+=s_r[i];
            atomicAdd(&g_psum[b*3+co], (double)s);
        }
        __syncthreads();
    }
}

// ---------------- SE gate ----------------
__global__ void k_se(const float* __restrict__ w1, const float* __restrict__ b1,
                     const float* __restrict__ w2, const float* __restrict__ b2){
    int t = threadIdx.x;
    if (t < NB){
        float p[3];
        #pragma unroll
        for (int c=0;c<3;c++) p[c] = (float)(g_psum[t*3+c] * (1.0/262144.0));
        float h[4];
        #pragma unroll
        for (int j=0;j<4;j++){
            float a = b1[j];
            #pragma unroll
            for (int c=0;c<3;c++) a += w1[j*3+c]*p[c];
            h[j] = a/(1.f+__expf(-a));
        }
        #pragma unroll
        for (int c=0;c<3;c++){
            float a = b2[c];
            #pragma unroll
            for (int j=0;j<4;j++) a += w2[c*4+j]*h[j];
            g_wse[t*3+c] = 1.f/(1.f+__expf(-a));
        }
    }
}

// ---------------- final: 4px/thread, float4 ----------------
__global__ void k_final(const float* __restrict__ x, const float* __restrict__ alpha,
                        float* __restrict__ out){
    int i4 = (blockIdx.x*256 + threadIdx.x)*4;
    if (i4 >= NPIX) return;
    int bc = i4 / HW;
    float s = alpha[0]*g_wse[bc];
    float4 xv = *(const float4*)(&x[i4]);
    float4 dv = *(const float4*)(&g_delta[i4]);
    float4 o;
    o.x = xv.x + s*dv.x;
    o.y = xv.y + s*dv.y;
    o.z = xv.z + s*dv.z;
    o.w = xv.w + s*dv.w;
    *(float4*)(&out[i4]) = o;
}

// ---------------- launch ----------------
extern "C" void kernel_launch(void* const* d_in, const int* in_sizes, int n_in,
                              void* d_out, int out_size){
    const float* x    = (const float*)d_in[0];
    const float* ng   = (const float*)d_in[1];
    const float* nbv  = (const float*)d_in[2];
    const float* pw1  = (const float*)d_in[3];
    const float* pb1  = (const float*)d_in[4];
    const float* pw2  = (const float*)d_in[5];
    const float* pb2  = (const float*)d_in[6];
    const float* zw1  = (const float*)d_in[7];
    const float* zb1  = (const float*)d_in[8];
    const float* zw2  = (const float*)d_in[9];
    const float* zb2  = (const float*)d_in[10];
    const float* fg   = (const float*)d_in[11];
    const float* mw1  = (const float*)d_in[12];
    const float* mb1  = (const float*)d_in[13];
    const float* g1g  = (const float*)d_in[14];
    const float* g1b  = (const float*)d_in[15];
    const float* mw2  = (const float*)d_in[16];
    const float* mb2  = (const float*)d_in[17];
    const float* g2g  = (const float*)d_in[18];
    const float* g2b  = (const float*)d_in[19];
    const float* mw3  = (const float*)d_in[20];
    const float* mb3  = (const float*)d_in[21];
    const float* sw1  = (const float*)d_in[22];
    const float* sb1  = (const float*)d_in[23];
    const float* sw2  = (const float*)d_in[24];
    const float* sb2  = (const float*)d_in[25];
    const float* alpha= (const float*)d_in[26];

    const int SMEM_HO  = (612*40 + 2880)*2 + 8*4;              // 54752 B
    const int SMEM_MC2 = (18*34*CIP + 9*32*CIP)*2 + 96*4;      // 72384 B
    const int SMEM_MC1 = (16384 + 4608)*2 + 32*4;              // 42112 B
    cudaFuncSetAttribute(k_headout,  cudaFuncAttributeMaxDynamicSharedMemorySize, SMEM_HO);
    cudaFuncSetAttribute(k_mixconv2, cudaFuncAttributeMaxDynamicSharedMemorySize, SMEM_MC2);
    cudaFuncSetAttribute(k_mixconv1, cudaFuncAttributeMaxDynamicSharedMemorySize, SMEM_MC1);

    dim3 g16(32, 32, NB);       // 16x16 tiles (conv1)
    dim3 g32(16, 32, NB);       // 32x16 tiles (headout, mixconv1, mixconv2)
    k_init<<<1,256>>>();
    k_xstats1<<<dim3(48,NB),256>>>(x);
    k_xstats2<<<1,32>>>();
    k_conv1<<<g16,256>>>(x, ng, nbv, pw1, pb1, zw1, zb1);
    k_headout<<<g32,256,SMEM_HO>>>(x, pw2, pb2, zw2, zb2);
    k_fftrow_fwd<<<NB*NC*512,256>>>();
    k_fftcol<<<NB*NC*64,256>>>(fg);
    k_ifftrow_mag<<<NB*NC*512,256>>>();
    k_mixconv1<<<g32,256,SMEM_MC1>>>(x, mw1, mb1);
    k_mixconv2<<<g32,256,SMEM_MC2>>>(mw2, mb2, g1g, g1b);
    k_mixconv3<<<dim3(HW/512, NB),256>>>(mw3, mb3, g2g, g2b);
    k_se<<<1,32>>>(sw1, sb1, sw2, sb2);
    k_final<<<NPIX/1024,256>>>(x, alpha, (float*)d_out);
}

// round 17
// speedup vs baseline: 1.2898x; 1.2898x over previous
#include <cuda_runtime.h>
#include <cuda_fp16.h>
#include <math.h>

#define HH 512
#define WW 512
#define HW (512*512)
#define NB 8
#define NC 3
#define NPIX (NB*NC*HW)
#define PI_F 3.14159265358979f
#define CIP 40

// ---------------- scratch (device globals; no allocations) ----------------
__device__ __half g_H16[NB*32*HW];      // 128 MB phase-head hidden (fp16)
__device__ __half g_Hb[NB*32*HW];       // 128 MB y1 (mix conv1 raw out)
__device__ __half g_Y2[NB*32*HW];       // 128 MB y2 (mix conv2 raw out)
__device__ float2 g_U[NB*NC*HW];        // 50 MB  complex field
__device__ __half g_J[NB*NC*HW];        // 12.5 MB (fp16)
__device__ float  g_delta[NB*NC*HW];    // 25 MB
__device__ float2 g_twid[256];
__device__ double g_zsum[NB*NC];
__device__ double g_xs1[NB], g_xs2[NB];
__device__ float  g_xmu[NB], g_xrs[NB];
__device__ double g_s1y1[NB], g_s2y1[NB], g_s1y2[NB], g_s2y2[NB];
__device__ double g_psum[NB*NC];
__device__ float  g_wse[NB*NC];

__device__ __forceinline__ int rev9(int x){ return (int)(__brev((unsigned)x) >> 23); }
__device__ __forceinline__ float siluf(float v){ return v / (1.f + __expf(-v)); }
__device__ __forceinline__ float warpSum(float v){
    #pragma unroll
    for (int o=16;o;o>>=1) v += __shfl_down_sync(0xffffffffu, v, o);
    return v;
}
// ---- packed f32x2 helpers ----
__device__ __forceinline__ unsigned long long pk2(float a, float b){
    unsigned long long r;
    asm("mov.b64 %0, {%1, %2};" : "=l"(r) : "f"(a), "f"(b));
    return r;
}
__device__ __forceinline__ void upk2(unsigned long long v, float& a, float& b){
    asm("mov.b64 {%0, %1}, %2;" : "=f"(a), "=f"(b) : "l"(v));
}
__device__ __forceinline__ void fma2(unsigned long long& d, unsigned long long a, unsigned long long b){
    asm("fma.rn.f32x2 %0, %1, %2, %3;" : "=l"(d) : "l"(a), "l"(b), "l"(d));
}
__device__ __forceinline__ unsigned pkh(float a, float b){
    __half2 h = __floats2half2_rn(a, b);
    return *(unsigned*)&h;
}
__device__ __forceinline__ unsigned pkh2(__half a, __half b){
    __half2 h = __halves2half2(a, b);
    return *(unsigned*)&h;
}
__device__ __forceinline__ void mma16816(float* acc, unsigned a0, unsigned a1,
                                         unsigned a2, unsigned a3, unsigned b0, unsigned b1){
    asm volatile(
        "mma.sync.aligned.m16n8k16.row.col.f32.f16.f16.f32 "
        "{%0,%1,%2,%3}, {%4,%5,%6,%7}, {%8,%9}, {%0,%1,%2,%3};"
        : "+f"(acc[0]), "+f"(acc[1]), "+f"(acc[2]), "+f"(acc[3])
        : "r"(a0), "r"(a1), "r"(a2), "r"(a3), "r"(b0), "r"(b1));
}

// ---------------- init ----------------
__global__ void k_init(){
    int t = threadIdx.x;
    if (t < 256){
        double ang = -2.0*3.14159265358979323846*(double)t/512.0;
        g_twid[t] = make_float2((float)cos(ang), (float)sin(ang));
    }
    if (t < NB*NC){ g_zsum[t]=0.0; g_psum[t]=0.0; }
    if (t < NB){
        g_s1y1[t]=0.0; g_s2y1[t]=0.0; g_s1y2[t]=0.0; g_s2y2[t]=0.0;
        g_xs1[t]=0.0; g_xs2[t]=0.0;
    }
}

// ---------------- x groupnorm stats (per batch), wide grid ----------------
__global__ void k_xstats1(const float* __restrict__ x){
    int b = blockIdx.y, t = threadIdx.x;
    const float4* p = (const float4*)(x + (size_t)b*NC*HW);
    float s=0.f, ss=0.f;
    for (int i = blockIdx.x*256 + t; i < NC*HW/4; i += 48*256){
        float4 v = p[i];
        s  += v.x+v.y+v.z+v.w;
        ss += v.x*v.x+v.y*v.y+v.z*v.z+v.w*v.w;
    }
    __shared__ float r1[8], r2[8];
    float w1 = warpSum(s), w2 = warpSum(ss);
    int lane=t&31, wid=t>>5;
    if (lane==0){ r1[wid]=w1; r2[wid]=w2; }
    __syncthreads();
    if (t==0){
        float a=0.f, bb=0.f;
        #pragma unroll
        for (int i=0;i<8;i++){ a+=r1[i]; bb+=r2[i]; }
        atomicAdd(&g_xs1[b], (double)a);
        atomicAdd(&g_xs2[b], (double)bb);
    }
}
__global__ void k_xstats2(){
    int t = threadIdx.x;
    if (t < NB){
        double N = (double)(NC*HW);
        double mu = g_xs1[t]/N;
        double var = g_xs2[t]/N - mu*mu;
        g_xmu[t] = (float)mu;
        g_xrs[t] = rsqrtf((float)var + 1e-5f);
    }
}

// ---- conv1 FFMA2 (validated): xn(3)->32ch silu fp16; 16x16 tile, 4px x 8co ----
__global__ __launch_bounds__(256,3) void k_conv1(const float* __restrict__ x,
                        const float* __restrict__ ng, const float* __restrict__ nbv,
                        const float* __restrict__ pw1, const float* __restrict__ pb1,
                        const float* __restrict__ zw1, const float* __restrict__ zb1){
    __shared__ __align__(16) float s_in[3*360];   // 3ci x 18row x 20col(pad)
    __shared__ __align__(16) float s_w[27*32];
    __shared__ float s_b[32];
    __shared__ float s_sc[3], s_sh[3];
    int b = blockIdx.z;
    int t = threadIdx.x;
    int qx = t&3, ty = (t>>2)&15, cg = t>>6;
    int oy0 = blockIdx.y*16, ox0 = blockIdx.x*16;
    if (t < 3){
        float rs = g_xrs[b], mu = g_xmu[b];
        s_sc[t] = ng[t]*rs;
        s_sh[t] = nbv[t] - mu*rs*ng[t];
    }
    for (int g=t; g<864; g+=256){
        int co=g/27, r=g%27;
        float w = (co<16) ? pw1[g] : zw1[(co-16)*27+r];
        s_w[r*32+co] = w;
    }
    if (t<32) s_b[t] = (t<16) ? pb1[t] : zb1[t-16];
    __syncthreads();
    for (int g=t; g<3*360; g+=256){
        int ci=g/360, r=g%360, iy=r/20, ix=r%20;
        int gy=oy0+iy-1, gx=ox0+ix-1;
        float v = 0.f;
        if (ix<18 && gy>=0 && gy<HH && gx>=0 && gx<WW)
            v = x[(size_t)(b*3+ci)*HW + gy*WW + gx]*s_sc[ci] + s_sh[ci];
        s_in[g] = v;
    }
    __syncthreads();
    unsigned long long acc[4][4];
    #pragma unroll
    for (int c=0;c<4;c++){
        unsigned long long bb = pk2(s_b[cg*8+2*c], s_b[cg*8+2*c+1]);
        #pragma unroll
        for (int p=0;p<4;p++) acc[c][p]=bb;
    }
    #pragma unroll
    for (int ci=0;ci<3;ci++)
    #pragma unroll
    for (int ky=0;ky<3;ky++){
        const float* row = s_in + ci*360 + (ty+ky)*20 + 4*qx;
        float4 f0 = *(const float4*)row;
        float2 f1 = *(const float2*)(row+4);
        unsigned long long vv[6];
        vv[0]=pk2(f0.x,f0.x); vv[1]=pk2(f0.y,f0.y); vv[2]=pk2(f0.z,f0.z);
        vv[3]=pk2(f0.w,f0.w); vv[4]=pk2(f1.x,f1.x); vv[5]=pk2(f1.y,f1.y);
        #pragma unroll
        for (int kx=0;kx<3;kx++){
            const unsigned long long* wr = (const unsigned long long*)(s_w + (ci*9+ky*3+kx)*32) + cg*4;
            #pragma unroll
            for (int c=0;c<4;c++){
                unsigned long long w = wr[c];
                fma2(acc[c][0], vv[kx],   w);
                fma2(acc[c][1], vv[kx+1], w);
                fma2(acc[c][2], vv[kx+2], w);
                fma2(acc[c][3], vv[kx+3], w);
            }
        }
    }
    int gy=oy0+ty, gx0=ox0+4*qx;
    size_t base = (size_t)b*32*HW + gy*WW + gx0;
    #pragma unroll
    for (int c=0;c<4;c++){
        int co0 = cg*8+2*c, co1 = co0+1;
        float a0[4], a1[4];
        #pragma unroll
        for (int p=0;p<4;p++) upk2(acc[c][p], a0[p], a1[p]);
        *(__half2*)(&g_H16[base + (size_t)co0*HW])     = __floats2half2_rn(siluf(a0[0]), siluf(a0[1]));
        *(__half2*)(&g_H16[base + (size_t)co0*HW + 2]) = __floats2half2_rn(siluf(a0[2]), siluf(a0[3]));
        *(__half2*)(&g_H16[base + (size_t)co1*HW])     = __floats2half2_rn(siluf(a1[0]), siluf(a1[1]));
        *(__half2*)(&g_H16[base + (size_t)co1*HW + 2]) = __floats2half2_rn(siluf(a1[2]), siluf(a1[3]));
    }
}

// -------- ph2 (phi->U0) + z2: fp32 FFMA2, 16x32 tile, packed (p,z) smem (validated) --------
__global__ __launch_bounds__(256) void k_headout(const float* __restrict__ x,
                          const float* __restrict__ pw2, const float* __restrict__ pb2,
                          const float* __restrict__ zw2, const float* __restrict__ zb2){
    extern __shared__ unsigned long long s_pz[];   // 16 pairs x 612 (18x34), 8B each
    __shared__ unsigned long long s_wpz[432];
    __shared__ float s_bpz[6];
    __shared__ float s_r[3][8];
    int b = blockIdx.z;
    int t = threadIdx.x, tx=t&15, ty=t>>4;
    int oy0 = blockIdx.y*16, ox0 = blockIdx.x*32;
    for (int g=t; g<432; g+=256){
        int r=g/3, co=g%3;
        s_wpz[r*3+co] = pk2(pw2[co*144+r], zw2[co*144+r]);
    }
    if (t<3){ s_bpz[t]=pb2[t]; s_bpz[3+t]=zb2[t]; }
    for (int g=t; g<16*612; g+=256){
        int cp=g/612, e=g%612, iy=e/34, ix=e%34;
        int gy=oy0+iy-1, gx=ox0+ix-1;
        float vp=0.f, vz=0.f;
        if (gy>=0 && gy<HH && gx>=0 && gx<WW){
            size_t p = (size_t)(b*32+cp)*HW + gy*WW + gx;
            vp = __half2float(g_H16[p]);
            vz = __half2float(g_H16[p + (size_t)16*HW]);
        }
        s_pz[g] = pk2(vp, vz);
    }
    __syncthreads();
    unsigned long long apz0[3], apz1[3];
    #pragma unroll
    for (int c=0;c<3;c++){
        unsigned long long bb = pk2(s_bpz[c], s_bpz[3+c]);
        apz0[c]=bb; apz1[c]=bb;
    }
    #pragma unroll
    for (int cp=0;cp<16;cp++)
    #pragma unroll
    for (int ky=0;ky<3;ky++)
    #pragma unroll
    for (int kx=0;kx<3;kx++){
        int off = cp*612 + (ty+ky)*34 + tx+kx;
        unsigned long long v0 = s_pz[off];
        unsigned long long v1 = s_pz[off + 16];
        int r = cp*9+ky*3+kx;
        #pragma unroll
        for (int c=0;c<3;c++){
            unsigned long long w = s_wpz[r*3+c];
            fma2(apz0[c], v0, w);
            fma2(apz1[c], v1, w);
        }
    }
    int gy=oy0+ty;
    float zl[3];
    #pragma unroll
    for (int c=0;c<3;c++){
        float ap0, az0, ap1, az1;
        upk2(apz0[c], ap0, az0);
        upk2(apz1[c], ap1, az1);
        size_t p0 = (size_t)(b*3+c)*HW + gy*WW + ox0+tx;
        size_t p1 = p0 + 16;
        float phi0 = tanhf(ap0)*PI_F, phi1 = tanhf(ap1)*PI_F;
        float xv0 = x[p0], xv1 = x[p1];
        float sn, cs;
        __sincosf(phi0, &sn, &cs);
        g_U[p0] = make_float2(xv0*cs, xv0*sn);
        __sincosf(phi1, &sn, &cs);
        g_U[p1] = make_float2(xv1*cs, xv1*sn);
        zl[c] = 0.3f/(1.f+__expf(-az0)) + 0.3f/(1.f+__expf(-az1));
    }
    int lane=t&31, wid=t>>5;
    #pragma unroll
    for (int c=0;c<3;c++){
        float ws = warpSum(zl[c]);
        if (lane==0) s_r[c][wid]=ws;
    }
    __syncthreads();
    if (t==0){
        #pragma unroll
        for (int c=0;c<3;c++){
            float s=0.f;
            #pragma unroll
            for (int i=0;i<8;i++) s+=s_r[c][i];
            atomicAdd(&g_zsum[b*3+c], (double)s);
        }
    }
}

// ---------------- 512-pt FFT core (AoS, rows) ----------------
__device__ __forceinline__ void fft512(float2* s, const float2* tw, int t, bool inv){
    #pragma unroll
    for (int st=1; st<=9; st++){
        int half = 1<<(st-1);
        int grp = t >> (st-1);
        int j   = t & (half-1);
        int i   = (grp << st) + j;
        float2 w = tw[j << (9-st)];
        float wy = inv ? -w.y : w.y;
        float2 u = s[i], v = s[i+half];
        float vr = v.x*w.x - v.y*wy;
        float vi = v.x*wy + v.y*w.x;
        s[i]      = make_float2(u.x+vr, u.y+vi);
        s[i+half] = make_float2(u.x-vr, u.y-vi);
        __syncthreads();
    }
}

__global__ void k_fftrow_fwd(){
    __shared__ float2 s[512];
    __shared__ float2 tw[256];
    int t = threadIdx.x;
    size_t base = (size_t)blockIdx.x * 512;
    tw[t] = g_twid[t];
    float2 a = g_U[base+t], b = g_U[base+t+256];
    s[rev9(t)] = a; s[rev9(t+256)] = b;
    __syncthreads();
    fft512(s, tw, t, false);
    g_U[base+t] = s[t]; g_U[base+t+256] = s[t+256];
}

__global__ void k_ifftrow_mag(){
    __shared__ float2 s[512];
    __shared__ float2 tw[256];
    int t = threadIdx.x;
    size_t base = (size_t)blockIdx.x * 512;
    tw[t] = g_twid[t];
    float2 a = g_U[base+t], b = g_U[base+t+256];
    s[rev9(t)] = a; s[rev9(t+256)] = b;
    __syncthreads();
    fft512(s, tw, t, true);
    const float sc = 1.f/262144.f;
    #pragma unroll
    for (int e2=0;e2<2;e2++){
        int e = t + e2*256;
        float re = s[e].x*sc, im = s[e].y*sc;
        g_J[base+e] = __float2half(sqrtf(fmaxf(re*re+im*im, 1e-12f)));
    }
}

// ------- col FFT fwd + freq filter + col IFFT (8 cols/block, SoA pad 9) -------
__global__ void k_fftcol(const float* __restrict__ freq_gain){
    __shared__ float sRe[4608], sIm[4608];
    __shared__ float2 tw[256];
    int bid = blockIdx.x;
    int bc = bid>>6, cb = bid&63;
    int c = bc%3;
    int t = threadIdx.x;
    int cc = t&7, lr = t>>3;
    int col = cb*8 + cc;
    size_t base = (size_t)bc*HW;
    tw[t] = g_twid[t];
    #pragma unroll
    for (int k=0;k<16;k++){
        int r = lr + 32*k;
        float2 v = g_U[base + (size_t)r*WW + col];
        int rr = rev9(r);
        sRe[rr*9+cc] = v.x; sIm[rr*9+cc] = v.y;
    }
    __syncthreads();
    #pragma unroll
    for (int st=1; st<=9; st++){
        int half = 1<<(st-1);
        #pragma unroll
        for (int k=0;k<8;k++){
            int bf = lr + 32*k;
            int grp = bf >> (st-1), j = bf & (half-1);
            int i = (grp<<st) + j;
            float2 w = tw[j << (9-st)];
            int e0 = i*9+cc, e1 = (i+half)*9+cc;
            float ur=sRe[e0], ui=sIm[e0], vr0=sRe[e1], vi0=sIm[e1];
            float vr = vr0*w.x - vi0*w.y;
            float vi = vr0*w.y + vi0*w.x;
            sRe[e0]=ur+vr; sIm[e0]=ui+vi;
            sRe[e1]=ur-vr; sIm[e1]=ui-vi;
        }
        __syncthreads();
    }
    const float lam2inv = (c==0) ? (1.f/(0.65f*0.65f)) : (c==1) ? (1.f/(0.53f*0.53f)) : (1.f/(0.47f*0.47f));
    float zm = (float)(g_zsum[bc] * (1.0/262144.0));
    float gain = 1.f + freq_gain[c];
    float fx = (float)((col<256)?col:col-512) * (1.f/512.f);
    float fx2 = fx*fx;
    #pragma unroll
    for (int k=0;k<16;k++){
        int r = lr + 32*k;
        float fy = (float)((r<256)?r:r-512) * (1.f/512.f);
        float f2 = fy*fy + fx2;
        float kz = 6.28318530717958f * sqrtf(fmaxf(lam2inv - f2, 0.f));
        float hp = kz*zm;
        float sn, cs; __sincosf(hp, &sn, &cs);
        int e = r*9+cc;
        float re=sRe[e], im=sIm[e];
        sRe[e] = gain*(re*cs - im*sn);
        sIm[e] = gain*(re*sn + im*cs);
    }
    __syncthreads();
    #pragma unroll
    for (int k=0;k<16;k++){
        int r = lr + 32*k;
        int r2 = rev9(r);
        if (r < r2){
            int e=r*9+cc, e2=r2*9+cc;
            float a=sRe[e]; sRe[e]=sRe[e2]; sRe[e2]=a;
            float bb=sIm[e]; sIm[e]=sIm[e2]; sIm[e2]=bb;
        }
    }
    __syncthreads();
    #pragma unroll
    for (int st=1; st<=9; st++){
        int half = 1<<(st-1);
        #pragma unroll
        for (int k=0;k<8;k++){
            int bf = lr + 32*k;
            int grp = bf >> (st-1), j = bf & (half-1);
            int i = (grp<<st) + j;
            float2 w = tw[j << (9-st)];
            float wy = -w.y;
            int e0 = i*9+cc, e1 = (i+half)*9+cc;
            float ur=sRe[e0], ui=sIm[e0], vr0=sRe[e1], vi0=sIm[e1];
            float vr = vr0*w.x - vi0*wy;
            float vi = vr0*wy + vi0*w.x;
            sRe[e0]=ur+vr; sIm[e0]=ui+vi;
            sRe[e1]=ur-vr; sIm[e1]=ui-vi;
        }
        __syncthreads();
    }
    #pragma unroll
    for (int k=0;k<16;k++){
        int r = lr + 32*k;
        g_U[base + (size_t)r*WW + col] = make_float2(sRe[r*9+cc], sIm[r*9+cc]);
    }
}

// ---- mix conv1 via HMMA: [x,J_l,J_l-x_l](5, pad16) -> 32; 32x16 px tile ----
__global__ __launch_bounds__(256,2) void k_mixconv1(const float* __restrict__ x,
                           const float* __restrict__ w1, const float* __restrict__ b1){
    extern __shared__ __half smm1[];
    __half* s_in  = smm1;                   // [612][16]
    __half* s_out = smm1;                   // alias [32][512]
    __half* s_w   = smm1 + 16384;           // [tap9][co32][16]
    float*  s_b   = (float*)(s_w + 4608);
    __shared__ float s_r1[8], s_r2[8];
    int b = blockIdx.z;
    int t = threadIdx.x, w = t>>5, lane = t&31;
    int g = lane>>2, q = lane&3;
    int oy0 = blockIdx.y*16, ox0 = blockIdx.x*32;
    if (t<32) s_b[t]=b1[t];
    for (int e=t; e<4608; e+=256){
        int tap=e/512, r=e%512, co=r/16, ci=r%16;
        float v = (ci<5) ? w1[co*45 + ci*9 + tap] : 0.f;
        s_w[(tap*32+co)*16 + ci] = __float2half(v);
    }
    for (int e=t; e<612; e+=256){
        int iy=e/34, ix=e%34;
        int gy=oy0+iy-1, gx=ox0+ix-1;
        float x0=0,x1=0,x2=0,j0=0,j1=0,j2=0;
        if (gy>=0 && gy<HH && gx>=0 && gx<WW){
            size_t p = (size_t)b*3*HW + gy*WW + gx;
            x0=x[p]; x1=x[p+HW]; x2=x[p+2*HW];
            j0=__half2float(g_J[p]); j1=__half2float(g_J[p+HW]); j2=__half2float(g_J[p+2*HW]);
        }
        float xl = 0.299f*x0 + 0.587f*x1 + 0.114f*x2;
        float jl = 0.299f*j0 + 0.587f*j1 + 0.114f*j2;
        uint4* dst = (uint4*)(s_in + e*16);
        dst[0] = make_uint4(pkh(x0,x1), pkh(x2,jl), pkh(jl-xl,0.f), 0u);
        dst[1] = make_uint4(0u,0u,0u,0u);
    }
    __syncthreads();
    float acc[4][4][4];
    #pragma unroll
    for (int mt=0;mt<4;mt++)
    #pragma unroll
    for (int nt=0;nt<4;nt++)
    #pragma unroll
    for (int i=0;i<4;i++) acc[mt][nt][i]=0.f;
    #pragma unroll
    for (int tap=0; tap<9; tap++){
        int ky=tap/3, kx=tap%3;
        unsigned bf[4][2];
        #pragma unroll
        for (int nt=0;nt<4;nt++){
            const __half* wp = s_w + (tap*32 + nt*8 + g)*16 + q*2;
            bf[nt][0] = *(const unsigned*)(wp);
            bf[nt][1] = *(const unsigned*)(wp+8);
        }
        #pragma unroll
        for (int mt=0;mt<4;mt++){
            int yy = 2*w + (mt>>1) + ky;
            int xx = (mt&1)*16 + kx + g;
            const __half* ap = s_in + (yy*34 + xx)*16 + q*2;
            unsigned a0 = *(const unsigned*)ap;
            unsigned a1 = *(const unsigned*)(ap + 8*16);
            unsigned a2 = *(const unsigned*)(ap + 8);
            unsigned a3 = *(const unsigned*)(ap + 8*16 + 8);
            #pragma unroll
            for (int nt=0;nt<4;nt++)
                mma16816(acc[mt][nt], a0, a1, a2, a3, bf[nt][0], bf[nt][1]);
        }
    }
    float bias[4][2];
    #pragma unroll
    for (int nt=0;nt<4;nt++){
        bias[nt][0] = s_b[nt*8 + q*2];
        bias[nt][1] = s_b[nt*8 + q*2 + 1];
    }
    __syncthreads();
    float ls=0.f, lss=0.f;
    #pragma unroll
    for (int mt=0;mt<4;mt++){
        int yy = 2*w + (mt>>1);
        int x0 = (mt&1)*16;
        #pragma unroll
        for (int nt=0;nt<4;nt++){
            int co0 = nt*8 + q*2, co1 = co0+1;
            float v0 = acc[mt][nt][0] + bias[nt][0];
            float v1 = acc[mt][nt][1] + bias[nt][1];
            float v2 = acc[mt][nt][2] + bias[nt][0];
            float v3 = acc[mt][nt][3] + bias[nt][1];
            ls += v0+v1+v2+v3;
            lss += v0*v0+v1*v1+v2*v2+v3*v3;
            s_out[co0*512 + yy*32 + x0+g]   = __float2half(v0);
            s_out[co1*512 + yy*32 + x0+g]   = __float2half(v1);
            s_out[co0*512 + yy*32 + x0+g+8] = __float2half(v2);
            s_out[co1*512 + yy*32 + x0+g+8] = __float2half(v3);
        }
    }
    float w1s = warpSum(ls), w2s = warpSum(lss);
    if (lane==0){ s_r1[w]=w1s; s_r2[w]=w2s; }
    __syncthreads();
    if (t==0){
        float a=0.f, bb=0.f;
        #pragma unroll
        for (int i=0;i<8;i++){ a+=s_r1[i]; bb+=s_r2[i]; }
        atomicAdd(&g_s1y1[b], (double)a);
        atomicAdd(&g_s2y1[b], (double)bb);
    }
    for (int e=t; e<8192; e+=256){
        int co=e/256, r=e%256, yy=r/16, xh=r%16;
        *(__half2*)(&g_Hb[(size_t)(b*32+co)*HW + (size_t)(oy0+yy)*WW + ox0 + xh*2]) =
            *(const __half2*)(&s_out[co*512 + yy*32 + xh*2]);
    }
}

// ----- mix conv2: HMMA m16n8k16; 32x16 px tile, 9 shifted GEMMs, fp16 in/out -----
__global__ __launch_bounds__(256,2) void k_mixconv2(const float* __restrict__ w2, const float* __restrict__ b2,
                        const float* __restrict__ g1g, const float* __restrict__ g1b){
    extern __shared__ __half smh2[];
    __half* s_in = smh2;                         // [iy18][ix34][CIP40] halfs
    __half* s_w  = smh2 + 18*34*CIP;             // [tap9][co32][CIP40] halfs
    float*  s_A  = (float*)(s_w + 9*32*CIP);     // 32
    float*  s_B  = s_A + 32;                     // 32
    float*  s_bi = s_B + 32;                     // 32
    __shared__ float s_r1[8], s_r2[8];
    int b = blockIdx.z;
    int t = threadIdx.x, w = t>>5, lane = t&31;
    int g = lane>>2, q = lane&3;
    int oy0 = blockIdx.y*16, ox0 = blockIdx.x*32;
    if (t<32){
        double N = 8388608.0;
        double mu = g_s1y1[b]/N;
        double var = g_s2y1[b]/N - mu*mu;
        float rs = rsqrtf((float)var + 1e-5f);
        float A = rs*g1g[t];
        s_A[t]=A; s_B[t]=g1b[t]-(float)mu*A;
        s_bi[t]=b2[t];
    }
    for (int e=t; e<9216; e+=256){
        int co=e/288, r=e%288, ci=r/9, tap=r%9;
        s_w[(tap*32+co)*CIP + ci] = __float2half(w2[e]);
    }
    __syncthreads();
    for (int e=t; e<612; e+=256){
        int iy=e/34, ix=e%34;
        int gy=oy0+iy-1, gx=ox0+ix-1;
        bool in = (gy>=0 && gy<HH && gx>=0 && gx<WW);
        size_t p0 = (size_t)b*32*HW + (size_t)gy*WW + gx;
        float f[32];
        #pragma unroll
        for (int ci=0;ci<32;ci++){
            float v=0.f;
            if (in){
                float y = __half2float(g_Hb[p0 + (size_t)ci*HW]);
                v = siluf(y*s_A[ci] + s_B[ci]);
            }
            f[ci]=v;
        }
        uint4* dst = (uint4*)(s_in + e*CIP);
        #pragma unroll
        for (int k2=0;k2<4;k2++)
            dst[k2] = make_uint4(pkh(f[k2*8],f[k2*8+1]),   pkh(f[k2*8+2],f[k2*8+3]),
                                 pkh(f[k2*8+4],f[k2*8+5]), pkh(f[k2*8+6],f[k2*8+7]));
    }
    __syncthreads();
    float acc[4][4][4];
    #pragma unroll
    for (int mt=0;mt<4;mt++)
    #pragma unroll
    for (int nt=0;nt<4;nt++)
    #pragma unroll
    for (int i=0;i<4;i++) acc[mt][nt][i]=0.f;
    #pragma unroll
    for (int tap=0; tap<9; tap++){
        int ky=tap/3, kx=tap%3;
        #pragma unroll
        for (int kc=0; kc<2; kc++){
            unsigned bf[4][2];
            #pragma unroll
            for (int nt=0;nt<4;nt++){
                const __half* wp = s_w + (tap*32 + nt*8 + g)*CIP + kc*16 + q*2;
                bf[nt][0] = *(const unsigned*)(wp);
                bf[nt][1] = *(const unsigned*)(wp+8);
            }
            #pragma unroll
            for (int mt=0;mt<4;mt++){
                int yy = 2*w + (mt>>1) + ky;
                int xx = (mt&1)*16 + kx + g;
                const __half* ap = s_in + (yy*34 + xx)*CIP + kc*16 + q*2;
                unsigned a0 = *(const unsigned*)ap;
                unsigned a1 = *(const unsigned*)(ap + 8*CIP);
                unsigned a2 = *(const unsigned*)(ap + 8);
                unsigned a3 = *(const unsigned*)(ap + 8*CIP + 8);
                #pragma unroll
                for (int nt=0;nt<4;nt++)
                    mma16816(acc[mt][nt], a0, a1, a2, a3, bf[nt][0], bf[nt][1]);
            }
        }
    }
    float bias[4][2];
    #pragma unroll
    for (int nt=0;nt<4;nt++){
        bias[nt][0] = s_bi[nt*8 + q*2];
        bias[nt][1] = s_bi[nt*8 + q*2 + 1];
    }
    __syncthreads();
    __half* s_out = s_in;   // [co][y16][x32]
    float ls=0.f, lss=0.f;
    #pragma unroll
    for (int mt=0;mt<4;mt++){
        int yy = 2*w + (mt>>1);
        int x0 = (mt&1)*16;
        #pragma unroll
        for (int nt=0;nt<4;nt++){
            int co0 = nt*8 + q*2, co1 = co0+1;
            float v0 = acc[mt][nt][0] + bias[nt][0];
            float v1 = acc[mt][nt][1] + bias[nt][1];
            float v2 = acc[mt][nt][2] + bias[nt][0];
            float v3 = acc[mt][nt][3] + bias[nt][1];
            ls += v0+v1+v2+v3;
            lss += v0*v0+v1*v1+v2*v2+v3*v3;
            s_out[co0*512 + yy*32 + x0+g]   = __float2half(v0);
            s_out[co1*512 + yy*32 + x0+g]   = __float2half(v1);
            s_out[co0*512 + yy*32 + x0+g+8] = __float2half(v2);
            s_out[co1*512 + yy*32 + x0+g+8] = __float2half(v3);
        }
    }
    float w1s = warpSum(ls), w2s = warpSum(lss);
    if (lane==0){ s_r1[w]=w1s; s_r2[w]=w2s; }
    __syncthreads();
    if (t==0){
        float a=0.f, bb=0.f;
        #pragma unroll
        for (int i=0;i<8;i++){ a+=s_r1[i]; bb+=s_r2[i]; }
        atomicAdd(&g_s1y2[b], (double)a);
        atomicAdd(&g_s2y2[b], (double)bb);
    }
    for (int e=t; e<8192; e+=256){
        int co=e/256, r=e%256, yy=r/16, xh=r%16;
        *(__half2*)(&g_Y2[(size_t)(b*32+co)*HW + (size_t)(oy0+yy)*WW + ox0 + xh*2]) =
            *(const __half2*)(&s_out[co*512 + yy*32 + xh*2]);
    }
}

// ---------------- mix conv3 (1x1) -> delta + per-channel mean; 2px/thread ----------------
__global__ void k_mixconv3(const float* __restrict__ w3, const float* __restrict__ b3,
                           const float* __restrict__ g2g, const float* __restrict__ g2b){
    __shared__ float s_w[96], s_b3[3], s_A[32], s_B[32];
    __shared__ float s_r[8];
    int b = blockIdx.y;
    int t = threadIdx.x;
    int pix = (blockIdx.x*256 + t)*2;
    if (t<32){
        double N = 8388608.0;
        double mu = g_s1y2[b]/N;
        double var = g_s2y2[b]/N - mu*mu;
        float rs = rsqrtf((float)var + 1e-5f);
        float A = rs*g2g[t];
        s_A[t]=A; s_B[t]=g2b[t]-(float)mu*A;
    }
    if (t<96) s_w[t]=w3[t];
    if (t<3)  s_b3[t]=b3[t];
    __syncthreads();
    float a0=s_b3[0], a1=s_b3[1], a2=s_b3[2];
    float b0=s_b3[0], b1=s_b3[1], b2v=s_b3[2];
    size_t base = (size_t)b*32*HW + pix;
    #pragma unroll
    for (int ci=0;ci<32;ci++){
        __half2 h = *(const __half2*)(&g_Y2[base + (size_t)ci*HW]);
        float2 y = __half22float2(h);
        float A = s_A[ci], B = s_B[ci];
        float v0 = siluf(y.x*A + B);
        float v1 = siluf(y.y*A + B);
        float w0=s_w[ci], w1=s_w[32+ci], w2=s_w[64+ci];
        a0 += w0*v0; a1 += w1*v0; a2 += w2*v0;
        b0 += w0*v1; b1 += w1*v1; b2v += w2*v1;
    }
    size_t dbase = (size_t)b*3*HW + pix;
    *(float2*)(&g_delta[dbase])        = make_float2(a0, b0);
    *(float2*)(&g_delta[dbase+HW])     = make_float2(a1, b1);
    *(float2*)(&g_delta[dbase+2*HW])   = make_float2(a2, b2v);
    float av[3] = {a0+b0, a1+b1, a2+b2v};
    int lane=t&31, wid=t>>5;
    #pragma unroll
    for (int co=0;co<3;co++){
        float ws = warpSum(av[co]);
        if (lane==0) s_r[wid]=ws;
        __syncthreads();
        if (t==0){
            float s=0.f;
            #pragma unroll
            for (int i=0;i<8;i++) s+=s_r[i];
            atomicAdd(&g_psum[b*3+co], (double)s);
        }
        __syncthreads();
    }
}

// ---------------- SE gate ----------------
__global__ void k_se(const float* __restrict__ w1, const float* __restrict__ b1,
                     const float* __restrict__ w2, const float* __restrict__ b2){
    int t = threadIdx.x;
    if (t < NB){
        float p[3];
        #pragma unroll
        for (int c=0;c<3;c++) p[c] = (float)(g_psum[t*3+c] * (1.0/262144.0));
        float h[4];
        #pragma unroll
        for (int j=0;j<4;j++){
            float a = b1[j];
            #pragma unroll
            for (int c=0;c<3;c++) a += w1[j*3+c]*p[c];
            h[j] = a/(1.f+__expf(-a));
        }
        #pragma unroll
        for (int c=0;c<3;c++){
            float a = b2[c];
            #pragma unroll
            for (int j=0;j<4;j++) a += w2[c*4+j]*h[j];
            g_wse[t*3+c] = 1.f/(1.f+__expf(-a));
        }
    }
}

// ---------------- final: 4px/thread, float4 ----------------
__global__ void k_final(const float* __restrict__ x, const float* __restrict__ alpha,
                        float* __restrict__ out){
    int i4 = (blockIdx.x*256 + threadIdx.x)*4;
    if (i4 >= NPIX) return;
    int bc = i4 / HW;
    float s = alpha[0]*g_wse[bc];
    float4 xv = *(const float4*)(&x[i4]);
    float4 dv = *(const float4*)(&g_delta[i4]);
    float4 o;
    o.x = xv.x + s*dv.x;
    o.y = xv.y + s*dv.y;
    o.z = xv.z + s*dv.z;
    o.w = xv.w + s*dv.w;
    *(float4*)(&out[i4]) = o;
}

// ---------------- launch ----------------
extern "C" void kernel_launch(void* const* d_in, const int* in_sizes, int n_in,
                              void* d_out, int out_size){
    const float* x    = (const float*)d_in[0];
    const float* ng   = (const float*)d_in[1];
    const float* nbv  = (const float*)d_in[2];
    const float* pw1  = (const float*)d_in[3];
    const float* pb1  = (const float*)d_in[4];
    const float* pw2  = (const float*)d_in[5];
    const float* pb2  = (const float*)d_in[6];
    const float* zw1  = (const float*)d_in[7];
    const float* zb1  = (const float*)d_in[8];
    const float* zw2  = (const float*)d_in[9];
    const float* zb2  = (const float*)d_in[10];
    const float* fg   = (const float*)d_in[11];
    const float* mw1  = (const float*)d_in[12];
    const float* mb1  = (const float*)d_in[13];
    const float* g1g  = (const float*)d_in[14];
    const float* g1b  = (const float*)d_in[15];
    const float* mw2  = (const float*)d_in[16];
    const float* mb2  = (const float*)d_in[17];
    const float* g2g  = (const float*)d_in[18];
    const float* g2b  = (const float*)d_in[19];
    const float* mw3  = (const float*)d_in[20];
    const float* mb3  = (const float*)d_in[21];
    const float* sw1  = (const float*)d_in[22];
    const float* sb1  = (const float*)d_in[23];
    const float* sw2  = (const float*)d_in[24];
    const float* sb2  = (const float*)d_in[25];
    const float* alpha= (const float*)d_in[26];

    const int SMEM_HO  = 16*612*8;                             // 78336 B
    const int SMEM_MC2 = (18*34*CIP + 9*32*CIP)*2 + 96*4;      // 72384 B
    const int SMEM_MC1 = (16384 + 4608)*2 + 32*4;              // 42112 B
    cudaFuncSetAttribute(k_headout,  cudaFuncAttributeMaxDynamicSharedMemorySize, SMEM_HO);
    cudaFuncSetAttribute(k_mixconv2, cudaFuncAttributeMaxDynamicSharedMemorySize, SMEM_MC2);
    cudaFuncSetAttribute(k_mixconv1, cudaFuncAttributeMaxDynamicSharedMemorySize, SMEM_MC1);

    dim3 g16(32, 32, NB);       // 16x16 tiles (conv1)
    dim3 g32(16, 32, NB);       // 32x16 tiles (headout, mixconv1, mixconv2)
    k_init<<<1,256>>>();
    k_xstats1<<<dim3(48,NB),256>>>(x);
    k_xstats2<<<1,32>>>();
    k_conv1<<<g16,256>>>(x, ng, nbv, pw1, pb1, zw1, zb1);
    k_headout<<<g32,256,SMEM_HO>>>(x, pw2, pb2, zw2, zb2);
    k_fftrow_fwd<<<NB*NC*512,256>>>();
    k_fftcol<<<NB*NC*64,256>>>(fg);
    k_ifftrow_mag<<<NB*NC*512,256>>>();
    k_mixconv1<<<g32,256,SMEM_MC1>>>(x, mw1, mb1);
    k_mixconv2<<<g32,256,SMEM_MC2>>>(mw2, mb2, g1g, g1b);
    k_mixconv3<<<dim3(HW/512, NB),256>>>(mw3, mb3, g2g, g2b);
    k_se<<<1,32>>>(sw1, sb1, sw2, sb2);
    k_final<<<NPIX/1024,256>>>(x, alpha, (float*)d_out);
}